// round 1
// baseline (speedup 1.0000x reference)
#include <cuda_runtime.h>
#include <cuda_bf16.h>
#include <cstdint>
#include <cstddef>

// Problem constants
#define BB 8
#define TT 1024
#define CC 1024
#define MM (BB*TT)          // 8192 rows
#define C4 (4*CC)           // 4096

// ---------------------------------------------------------------------------
// Scratch (static __device__ arrays; no allocation allowed)
// ---------------------------------------------------------------------------
__device__ float g_xn [MM*CC];   // ln output (reused for ln2)
__device__ float g_r  [MM*CC];   // r, then r*wkv
__device__ float g_k  [MM*CC];
__device__ float g_v  [MM*CC];   // v, then sigmoid(xn2 Wfr^T)
__device__ float g_wf [MM*CC];
__device__ float g_wb [MM*CC];
__device__ float g_kk [MM*C4];   // ffn hidden

// ---------------------------------------------------------------------------
// Helpers
// ---------------------------------------------------------------------------
__device__ __forceinline__ uint32_t f2tf(float f) {
    uint32_t r;
    asm("cvt.rna.tf32.f32 %0, %1;" : "=r"(r) : "f"(f));
    return r;
}

__device__ __forceinline__ void cp_async16(void* sm, const void* gm) {
    uint32_t sa = (uint32_t)__cvta_generic_to_shared(sm);
    asm volatile("cp.async.cg.shared.global [%0], [%1], 16;\n" :: "r"(sa), "l"(gm));
}
__device__ __forceinline__ void cp_commit() {
    asm volatile("cp.async.commit_group;\n");
}
template <int N>
__device__ __forceinline__ void cp_wait() {
    asm volatile("cp.async.wait_group %0;\n" :: "n"(N));
}

__device__ __forceinline__ void mma_tf32(float* c, const uint32_t* a, const uint32_t* b) {
    asm volatile(
        "mma.sync.aligned.m16n8k8.row.col.f32.tf32.tf32.f32 "
        "{%0,%1,%2,%3}, {%4,%5,%6,%7}, {%8,%9}, {%0,%1,%2,%3};\n"
        : "+f"(c[0]), "+f"(c[1]), "+f"(c[2]), "+f"(c[3])
        : "r"(a[0]), "r"(a[1]), "r"(a[2]), "r"(a[3]),
          "r"(b[0]), "r"(b[1]));
}

// ---------------------------------------------------------------------------
// LayerNorm: one block per row (C=1024, 256 threads)
// ---------------------------------------------------------------------------
__global__ void ln_kernel(const float* __restrict__ x,
                          const float* __restrict__ w,
                          const float* __restrict__ b,
                          float* __restrict__ out) {
    int row = blockIdx.x;
    const float* xr = x + (size_t)row * CC;
    float s = 0.f, s2 = 0.f;
    float vals[4];
    #pragma unroll
    for (int i = 0; i < 4; i++) {
        float t = xr[threadIdx.x + i * 256];
        vals[i] = t;
        s += t; s2 += t * t;
    }
    #pragma unroll
    for (int o = 16; o; o >>= 1) {
        s  += __shfl_xor_sync(0xffffffffu, s,  o);
        s2 += __shfl_xor_sync(0xffffffffu, s2, o);
    }
    __shared__ float sh[34];
    int warp = threadIdx.x >> 5, lane = threadIdx.x & 31;
    if (lane == 0) { sh[warp] = s; sh[warp + 8] = s2; }
    __syncthreads();
    if (threadIdx.x < 32) {
        s  = (threadIdx.x < 8) ? sh[threadIdx.x]     : 0.f;
        s2 = (threadIdx.x < 8) ? sh[threadIdx.x + 8] : 0.f;
        #pragma unroll
        for (int o = 4; o; o >>= 1) {
            s  += __shfl_xor_sync(0xffffffffu, s,  o);
            s2 += __shfl_xor_sync(0xffffffffu, s2, o);
        }
        if (threadIdx.x == 0) {
            float mu  = s * (1.f / CC);
            float var = s2 * (1.f / CC) - mu * mu;
            sh[32] = mu;
            sh[33] = rsqrtf(var + 1e-5f);
        }
    }
    __syncthreads();
    float mu = sh[32], rs = sh[33];
    float* orow = out + (size_t)row * CC;
    #pragma unroll
    for (int i = 0; i < 4; i++) {
        int col = threadIdx.x + i * 256;
        orow[col] = (vals[i] - mu) * rs * w[col] + b[col];
    }
}

// ---------------------------------------------------------------------------
// WKV scan: one thread per (dir, b, c). grid (32, 2) x 256 threads
// ---------------------------------------------------------------------------
__global__ void scan_kernel(const float* __restrict__ decay,
                            const float* __restrict__ u,
                            const float* __restrict__ k,
                            const float* __restrict__ v,
                            float* __restrict__ wf,
                            float* __restrict__ wb) {
    int idx = blockIdx.x * blockDim.x + threadIdx.x;   // 0..8191
    int dir = blockIdx.y;
    int c = idx & (CC - 1);
    int bidx = idx >> 10;
    float w  = -__expf(decay[c]);
    float uu = u[c];
    float aa = 0.f, bbv = 0.f, pp = -1e38f;
    int base = bidx * (TT * CC) + c;
    int off, dt;
    float* o;
    if (dir == 0) { off = base;                  dt =  CC; o = wf; }
    else          { off = base + (TT - 1) * CC;  dt = -CC; o = wb; }
    for (int t = 0; t < TT; ++t, off += dt) {
        float kk = k[off], vv = v[off];
        float uk = uu + kk;
        float q  = fmaxf(pp, uk);
        float e1 = __expf(pp - q), e2 = __expf(uk - q);
        o[off] = (e1 * aa + e2 * vv) / (e1 * bbv + e2);
        float pw = pp + w;
        float q2 = fmaxf(pw, kk);
        float f1 = __expf(pw - q2), f2 = __expf(kk - q2);
        aa  = f1 * aa  + f2 * vv;
        bbv = f1 * bbv + f2;
        pp  = q2;
    }
}

// mix: r <- r * 0.5 * (wf + wb)
__global__ void mix_kernel(float* __restrict__ r,
                           const float* __restrict__ wf,
                           const float* __restrict__ wb) {
    int i = blockIdx.x * blockDim.x + threadIdx.x;
    r[i] = r[i] * 0.5f * (wf[i] + wb[i]);
}

// ---------------------------------------------------------------------------
// TF32 GEMM: C[M,N] = epilogue( A[M,K] * B[N,K]^T )
// 128x128x32 tiles, 256 threads, double-buffered cp.async, mma.m16n8k8.tf32
// ---------------------------------------------------------------------------
#define EPI_NONE    0
#define EPI_SIGMOID 1
#define EPI_RELU2   2
#define EPI_ADD     3
#define EPI_MADD    4

template <int EPI>
__global__ __launch_bounds__(256)
void gemm_tf32_kernel(const float* __restrict__ A,
                      const float* __restrict__ Bw,
                      float* __restrict__ Cout,
                      const float* __restrict__ aux1,
                      const float* __restrict__ aux2,
                      int M, int N, int K) {
    const int BM = 128, BN = 128, BK = 32, LDS = BK + 4; // 36
    extern __shared__ float smem[];
    float* Asm[2] = { smem,               smem + BM * LDS };
    float* Bsm[2] = { smem + 2 * BM * LDS, smem + 2 * BM * LDS + BN * LDS };

    int tid  = threadIdx.x;
    int bm   = blockIdx.y * BM;
    int bn   = blockIdx.x * BN;
    int warp = tid >> 5, lane = tid & 31;
    int g    = lane >> 2, q = lane & 3;
    int wm   = (warp >> 1) * 32;
    int wn   = (warp & 1) * 64;

    float acc[2][8][4];
    #pragma unroll
    for (int mt = 0; mt < 2; mt++)
        #pragma unroll
        for (int nt = 0; nt < 8; nt++)
            #pragma unroll
            for (int i = 0; i < 4; i++)
                acc[mt][nt][i] = 0.f;

    // precompute per-thread load coords: 4 iters, 128 rows x 8 float4 per tile
    const int nK = K / BK;

    // prologue: load tile 0 into stage 0
    {
        const float* Ag = A  + (size_t)bm * K;
        const float* Bg = Bw + (size_t)bn * K;
        #pragma unroll
        for (int i = 0; i < 4; i++) {
            int id = tid + i * 256;
            int row = id >> 3, sl = (id & 7) * 4;
            cp_async16(&Asm[0][row * LDS + sl], Ag + (size_t)row * K + sl);
            cp_async16(&Bsm[0][row * LDS + sl], Bg + (size_t)row * K + sl);
        }
        cp_commit();
    }

    for (int t = 0; t < nK; ++t) {
        int cur = t & 1;
        if (t + 1 < nK) {
            int nxt = (t + 1) & 1;
            const float* Ag = A  + (size_t)bm * K + (t + 1) * BK;
            const float* Bg = Bw + (size_t)bn * K + (t + 1) * BK;
            #pragma unroll
            for (int i = 0; i < 4; i++) {
                int id = tid + i * 256;
                int row = id >> 3, sl = (id & 7) * 4;
                cp_async16(&Asm[nxt][row * LDS + sl], Ag + (size_t)row * K + sl);
                cp_async16(&Bsm[nxt][row * LDS + sl], Bg + (size_t)row * K + sl);
            }
            cp_commit();
            cp_wait<1>();
        } else {
            cp_wait<0>();
        }
        __syncthreads();

        float* as = Asm[cur];
        float* bs = Bsm[cur];
        #pragma unroll
        for (int kk = 0; kk < BK; kk += 8) {
            uint32_t af[2][4], bf[8][2];
            #pragma unroll
            for (int mt = 0; mt < 2; mt++) {
                int r0 = wm + mt * 16 + g;
                af[mt][0] = f2tf(as[r0       * LDS + kk + q]);
                af[mt][1] = f2tf(as[(r0 + 8) * LDS + kk + q]);
                af[mt][2] = f2tf(as[r0       * LDS + kk + q + 4]);
                af[mt][3] = f2tf(as[(r0 + 8) * LDS + kk + q + 4]);
            }
            #pragma unroll
            for (int nt = 0; nt < 8; nt++) {
                int n0 = wn + nt * 8 + g;
                bf[nt][0] = f2tf(bs[n0 * LDS + kk + q]);
                bf[nt][1] = f2tf(bs[n0 * LDS + kk + q + 4]);
            }
            #pragma unroll
            for (int mt = 0; mt < 2; mt++)
                #pragma unroll
                for (int nt = 0; nt < 8; nt++)
                    mma_tf32(acc[mt][nt], af[mt], bf[nt]);
        }
        __syncthreads();
    }

    // epilogue
    #pragma unroll
    for (int mt = 0; mt < 2; mt++) {
        #pragma unroll
        for (int nt = 0; nt < 8; nt++) {
            #pragma unroll
            for (int i = 0; i < 4; i++) {
                int row = bm + wm + mt * 16 + g + ((i >= 2) ? 8 : 0);
                int col = bn + wn + nt * 8 + q * 2 + (i & 1);
                size_t idx = (size_t)row * N + col;
                float a = acc[mt][nt][i];
                float o;
                if (EPI == EPI_NONE)         o = a;
                else if (EPI == EPI_SIGMOID) o = 1.f / (1.f + __expf(-a));
                else if (EPI == EPI_RELU2) { float tv = fmaxf(a, 0.f); o = tv * tv; }
                else if (EPI == EPI_ADD)     o = aux1[idx] + a;
                else /* EPI_MADD */          o = aux1[idx] + aux2[idx] * a;
                Cout[idx] = o;
            }
        }
    }
}

// ---------------------------------------------------------------------------
// Launch
// ---------------------------------------------------------------------------
extern "C" void kernel_launch(void* const* d_in, const int* in_sizes, int n_in,
                              void* d_out, int out_size) {
    const float* x     = (const float*)d_in[0];
    const float* ln1w  = (const float*)d_in[1];
    const float* ln1b  = (const float*)d_in[2];
    const float* ln2w  = (const float*)d_in[3];
    const float* ln2b  = (const float*)d_in[4];
    const float* Wr    = (const float*)d_in[5];
    const float* Wk    = (const float*)d_in[6];
    const float* Wv    = (const float*)d_in[7];
    const float* Wo    = (const float*)d_in[8];
    const float* decay = (const float*)d_in[9];
    const float* u     = (const float*)d_in[10];
    const float* Wfk   = (const float*)d_in[11];
    const float* Wfv   = (const float*)d_in[12];
    const float* Wfr   = (const float*)d_in[13];
    float* out = (float*)d_out;

    float *xn, *r, *k, *v, *wf, *wb, *kkb;
    cudaGetSymbolAddress((void**)&xn,  g_xn);
    cudaGetSymbolAddress((void**)&r,   g_r);
    cudaGetSymbolAddress((void**)&k,   g_k);
    cudaGetSymbolAddress((void**)&v,   g_v);
    cudaGetSymbolAddress((void**)&wf,  g_wf);
    cudaGetSymbolAddress((void**)&wb,  g_wb);
    cudaGetSymbolAddress((void**)&kkb, g_kk);

    const int smem = 2 * (128 * 36 + 128 * 36) * 4; // 73728 bytes
    cudaFuncSetAttribute(gemm_tf32_kernel<EPI_NONE>,    cudaFuncAttributeMaxDynamicSharedMemorySize, smem);
    cudaFuncSetAttribute(gemm_tf32_kernel<EPI_SIGMOID>, cudaFuncAttributeMaxDynamicSharedMemorySize, smem);
    cudaFuncSetAttribute(gemm_tf32_kernel<EPI_RELU2>,   cudaFuncAttributeMaxDynamicSharedMemorySize, smem);
    cudaFuncSetAttribute(gemm_tf32_kernel<EPI_ADD>,     cudaFuncAttributeMaxDynamicSharedMemorySize, smem);
    cudaFuncSetAttribute(gemm_tf32_kernel<EPI_MADD>,    cudaFuncAttributeMaxDynamicSharedMemorySize, smem);

    dim3 gC (CC / 128, MM / 128);   // (8, 64)
    dim3 g4C(C4 / 128, MM / 128);   // (32, 64)

    // 1) ln1
    ln_kernel<<<MM, 256>>>(x, ln1w, ln1b, xn);
    // 2) r, k, v projections
    gemm_tf32_kernel<EPI_SIGMOID><<<gC, 256, smem>>>(xn, Wr, r, nullptr, nullptr, MM, CC, CC);
    gemm_tf32_kernel<EPI_NONE>   <<<gC, 256, smem>>>(xn, Wk, k, nullptr, nullptr, MM, CC, CC);
    gemm_tf32_kernel<EPI_NONE>   <<<gC, 256, smem>>>(xn, Wv, v, nullptr, nullptr, MM, CC, CC);
    // 3) bidirectional wkv scan
    scan_kernel<<<dim3(BB * CC / 256, 2), 256>>>(decay, u, k, v, wf, wb);
    // 4) r <- r * 0.5*(wf+wb)
    mix_kernel<<<(MM * CC) / 256, 256>>>(r, wf, wb);
    // 5) out = x + (r*wkv) @ Wo^T
    gemm_tf32_kernel<EPI_ADD>    <<<gC, 256, smem>>>(r, Wo, out, x, nullptr, MM, CC, CC);
    // 6) ln2
    ln_kernel<<<MM, 256>>>(out, ln2w, ln2b, xn);
    // 7) kk = relu(xn2 @ Wfk^T)^2
    gemm_tf32_kernel<EPI_RELU2>  <<<g4C, 256, smem>>>(xn, Wfk, kkb, nullptr, nullptr, MM, C4, CC);
    // 8) s = sigmoid(xn2 @ Wfr^T)  (stored in v)
    gemm_tf32_kernel<EPI_SIGMOID><<<gC, 256, smem>>>(xn, Wfr, v, nullptr, nullptr, MM, CC, CC);
    // 9) out += s * (kk @ Wfv^T)
    gemm_tf32_kernel<EPI_MADD>   <<<gC, 256, smem>>>(kkb, Wfv, out, out, v, MM, CC, C4);
}

// round 5
// speedup vs baseline: 2.5961x; 2.5961x over previous
#include <cuda_runtime.h>
#include <cuda_fp16.h>
#include <cstdint>
#include <cstddef>

// Problem constants
#define BBATCH 8
#define TT 1024
#define CC 1024
#define MM (BBATCH*TT)          // 8192 rows
#define C4 (4*CC)               // 4096

// ---------------------------------------------------------------------------
// Scratch (static __device__ arrays; no allocation allowed)
// ---------------------------------------------------------------------------
__device__ float  g_r  [MM*CC];            // sigmoid(xn Wr^T), f32
__device__ float  g_k  [MM*CC];            // k, f32 (scan input)
__device__ float  g_v  [MM*CC];            // v, f32 (scan input); later sigmoid(xn2 Wfr^T)
__device__ float  g_wf [MM*CC];
__device__ float  g_wb [MM*CC];
__device__ __half g_xnh[MM*CC];            // fp16 LN output (GEMM A)
__device__ __half g_rh [MM*CC];            // fp16 r*wkv (GEMM A)
__device__ __half g_kkh[(size_t)MM*C4];    // fp16 ffn hidden (GEMM A)
// fp16 weight copies (GEMM B)
__device__ __half g_w1 [CC*CC];            // Wr
__device__ __half g_w2 [CC*CC];            // Wk
__device__ __half g_w3 [CC*CC];            // Wv
__device__ __half g_w4 [CC*CC];            // Wo
__device__ __half g_w5 [(size_t)C4*CC];    // Wfk
__device__ __half g_w6 [(size_t)CC*C4];    // Wfv
__device__ __half g_w7 [CC*CC];            // Wfr

// ---------------------------------------------------------------------------
// PTX helpers
// ---------------------------------------------------------------------------
__device__ __forceinline__ void cp_async16(uint32_t sa, const void* gm) {
    asm volatile("cp.async.cg.shared.global [%0], [%1], 16;" :: "r"(sa), "l"(gm));
}
__device__ __forceinline__ void ldsm_x4(uint32_t* r, uint32_t addr) {
    asm volatile("ldmatrix.sync.aligned.m8n8.x4.shared.b16 {%0,%1,%2,%3}, [%4];"
                 : "=r"(r[0]), "=r"(r[1]), "=r"(r[2]), "=r"(r[3]) : "r"(addr));
}
__device__ __forceinline__ void mma_f16(float* c, const uint32_t* a, const uint32_t* b) {
    asm volatile(
        "mma.sync.aligned.m16n8k16.row.col.f32.f16.f16.f32 "
        "{%0,%1,%2,%3}, {%4,%5,%6,%7}, {%8,%9}, {%0,%1,%2,%3};"
        : "+f"(c[0]), "+f"(c[1]), "+f"(c[2]), "+f"(c[3])
        : "r"(a[0]), "r"(a[1]), "r"(a[2]), "r"(a[3]), "r"(b[0]), "r"(b[1]));
}
__device__ __forceinline__ uint32_t sw128(uint32_t off) {
    return off ^ ((off >> 3) & 0x70);
}

// ---------------------------------------------------------------------------
// fp16 GEMM: C[M,N] = epilogue( A[M,K] * B[N,K]^T ), A/B fp16, accum f32
// CTA tile 128x128, BK=64 halves (128B rows, SW128), 2-stage cp.async,
// 256 threads (8 warps, 2x4), warp tile 64x32, ldmatrix + mma.m16n8k16
// ---------------------------------------------------------------------------
#define EPI_NONE    0
#define EPI_SIGMOID 1
#define EPI_RELU2   2   // writes fp16 (feeds next GEMM as A)
#define EPI_ADD     3
#define EPI_MADD    4

#define STG_BYTES 32768   // 16KB A (128x128B) + 16KB B

template <int EPI>
__global__ __launch_bounds__(256, 2)
void gemm_h(const __half* __restrict__ A, const __half* __restrict__ Bw,
            float* __restrict__ Cf, __half* __restrict__ Ch,
            const float* __restrict__ aux1, const float* __restrict__ aux2,
            int M, int N, int K)
{
    extern __shared__ char smem_raw[];
    const uint32_t sb = ((uint32_t)__cvta_generic_to_shared(smem_raw) + 127u) & ~127u;

    const int tid  = threadIdx.x;
    const int warp = tid >> 5;
    const int lane = tid & 31;
    const int bm   = blockIdx.y * 128;
    const int bn   = blockIdx.x * 128;
    const int wm   = (warp & 1) * 64;
    const int wn   = (warp >> 1) * 32;
    const int nK   = K >> 6;            // K tiles of 64 halves

    // per-lane ldmatrix source coordinates
    const int rowA = lane & 15;                      // + wm + mt*16
    const int kA   = (lane >> 4) << 3;               // 0 or 8 (halves)
    const int rowB = (lane & 7) + ((lane >> 4) << 3);// + wn + nt2*16
    const int kB   = ((lane >> 3) & 1) << 3;         // 0 or 8

    float acc[4][4][4];
    #pragma unroll
    for (int mt = 0; mt < 4; mt++)
        #pragma unroll
        for (int nt = 0; nt < 4; nt++)
            #pragma unroll
            for (int i = 0; i < 4; i++) acc[mt][nt][i] = 0.f;

    auto load_tile = [&](int kt, int s) {
        const __half* Ag = A  + (size_t)bm * K + kt * 64;
        const __half* Bg = Bw + (size_t)bn * K + kt * 64;
        uint32_t sA = sb + s * STG_BYTES;
        uint32_t sB = sA + 16384;
        #pragma unroll
        for (int i = 0; i < 4; i++) {          // 128 rows x 8 chunks of 16B
            int n = tid + i * 256;
            int row = n >> 3, c = n & 7;
            uint32_t sw = sw128((uint32_t)(row * 128 + c * 16));
            cp_async16(sA + sw, Ag + (size_t)row * K + c * 8);
            cp_async16(sB + sw, Bg + (size_t)row * K + c * 8);
        }
    };

    load_tile(0, 0);
    asm volatile("cp.async.commit_group;");

    for (int t = 0; t < nK; t++) {
        if (t + 1 < nK) {
            load_tile(t + 1, (t + 1) & 1);
            asm volatile("cp.async.commit_group;");
            asm volatile("cp.async.wait_group 1;");
        } else {
            asm volatile("cp.async.wait_group 0;");
        }
        __syncthreads();

        uint32_t sA = sb + (t & 1) * STG_BYTES;
        uint32_t sB = sA + 16384;

        #pragma unroll
        for (int ks = 0; ks < 4; ks++) {       // 4 x k16 per 64-half tile
            uint32_t a[4][4], b[4][2];
            #pragma unroll
            for (int mt = 0; mt < 4; mt++) {
                int r = wm + mt * 16 + rowA;
                uint32_t off = (uint32_t)(r * 128 + (ks * 16 + kA) * 2);
                ldsm_x4(a[mt], sA + sw128(off));
            }
            #pragma unroll
            for (int nt2 = 0; nt2 < 2; nt2++) {
                uint32_t rb[4];
                int n = wn + nt2 * 16 + rowB;
                uint32_t off = (uint32_t)(n * 128 + (ks * 16 + kB) * 2);
                ldsm_x4(rb, sB + sw128(off));
                b[nt2 * 2][0]     = rb[0]; b[nt2 * 2][1]     = rb[1];
                b[nt2 * 2 + 1][0] = rb[2]; b[nt2 * 2 + 1][1] = rb[3];
            }
            #pragma unroll
            for (int mt = 0; mt < 4; mt++)
                #pragma unroll
                for (int nt = 0; nt < 4; nt++)
                    mma_f16(acc[mt][nt], a[mt], b[nt]);
        }
        __syncthreads();
    }

    // ---------------- epilogue (direct from registers) ---------------------
    const int g = lane >> 2, q = lane & 3;
    #pragma unroll
    for (int mt = 0; mt < 4; mt++) {
        #pragma unroll
        for (int half = 0; half < 2; half++) {
            int row = bm + wm + mt * 16 + g + half * 8;
            #pragma unroll
            for (int nt = 0; nt < 4; nt++) {
                int col = bn + wn + nt * 8 + q * 2;
                size_t gi = (size_t)row * N + col;
                float c0 = acc[mt][nt][half * 2];
                float c1 = acc[mt][nt][half * 2 + 1];
                if (EPI == EPI_NONE) {
                    *(float2*)(Cf + gi) = make_float2(c0, c1);
                } else if (EPI == EPI_SIGMOID) {
                    *(float2*)(Cf + gi) = make_float2(1.f / (1.f + __expf(-c0)),
                                                      1.f / (1.f + __expf(-c1)));
                } else if (EPI == EPI_RELU2) {
                    float t0 = fmaxf(c0, 0.f), t1 = fmaxf(c1, 0.f);
                    *(__half2*)(Ch + gi) = __floats2half2_rn(t0 * t0, t1 * t1);
                } else if (EPI == EPI_ADD) {
                    float2 a2 = *(const float2*)(aux1 + gi);
                    *(float2*)(Cf + gi) = make_float2(a2.x + c0, a2.y + c1);
                } else { // EPI_MADD
                    float2 a2 = *(const float2*)(aux1 + gi);
                    float2 s2 = *(const float2*)(aux2 + gi);
                    *(float2*)(Cf + gi) = make_float2(a2.x + s2.x * c0,
                                                      a2.y + s2.y * c1);
                }
            }
        }
    }
}

// ---------------------------------------------------------------------------
// Weight conversion f32 -> fp16 (once per launch)
// ---------------------------------------------------------------------------
__global__ void cvt_h_kernel(const float* __restrict__ s, __half* __restrict__ d) {
    int i = (blockIdx.x * blockDim.x + threadIdx.x) * 4;
    float4 v = *(const float4*)(s + i);
    __half2 h0 = __floats2half2_rn(v.x, v.y);
    __half2 h1 = __floats2half2_rn(v.z, v.w);
    *(__half2*)(d + i)     = h0;
    *(__half2*)(d + i + 2) = h1;
}

// ---------------------------------------------------------------------------
// LayerNorm: one block per row (C=1024, 256 threads); fp16 output
// ---------------------------------------------------------------------------
__global__ void ln_kernel(const float* __restrict__ x,
                          const float* __restrict__ w,
                          const float* __restrict__ b,
                          __half* __restrict__ out) {
    int row = blockIdx.x;
    const float* xr = x + (size_t)row * CC;
    float s = 0.f, s2 = 0.f;
    float vals[4];
    #pragma unroll
    for (int i = 0; i < 4; i++) {
        float t = xr[threadIdx.x + i * 256];
        vals[i] = t;
        s += t; s2 += t * t;
    }
    #pragma unroll
    for (int o = 16; o; o >>= 1) {
        s  += __shfl_xor_sync(0xffffffffu, s,  o);
        s2 += __shfl_xor_sync(0xffffffffu, s2, o);
    }
    __shared__ float sh[34];
    int warp = threadIdx.x >> 5, lane = threadIdx.x & 31;
    if (lane == 0) { sh[warp] = s; sh[warp + 8] = s2; }
    __syncthreads();
    if (threadIdx.x < 32) {
        s  = (threadIdx.x < 8) ? sh[threadIdx.x]     : 0.f;
        s2 = (threadIdx.x < 8) ? sh[threadIdx.x + 8] : 0.f;
        #pragma unroll
        for (int o = 4; o; o >>= 1) {
            s  += __shfl_xor_sync(0xffffffffu, s,  o);
            s2 += __shfl_xor_sync(0xffffffffu, s2, o);
        }
        if (threadIdx.x == 0) {
            float mu  = s * (1.f / CC);
            float var = s2 * (1.f / CC) - mu * mu;
            sh[32] = mu;
            sh[33] = rsqrtf(var + 1e-5f);
        }
    }
    __syncthreads();
    float mu = sh[32], rs = sh[33];
    __half* orow = out + (size_t)row * CC;
    #pragma unroll
    for (int i = 0; i < 4; i++) {
        int col = threadIdx.x + i * 256;
        orow[col] = __float2half_rn((vals[i] - mu) * rs * w[col] + b[col]);
    }
}

// ---------------------------------------------------------------------------
// WKV scan: one thread per (dir, b, c)
// ---------------------------------------------------------------------------
__global__ void scan_kernel(const float* __restrict__ decay,
                            const float* __restrict__ u,
                            const float* __restrict__ k,
                            const float* __restrict__ v,
                            float* __restrict__ wf,
                            float* __restrict__ wb) {
    int idx = blockIdx.x * blockDim.x + threadIdx.x;   // 0..8191
    int dir = blockIdx.y;
    int c = idx & (CC - 1);
    int bidx = idx >> 10;
    float w  = -__expf(decay[c]);
    float uu = u[c];
    float aa = 0.f, bbv = 0.f, pp = -1e38f;
    int base = bidx * (TT * CC) + c;
    int off, dt;
    float* o;
    if (dir == 0) { off = base;                  dt =  CC; o = wf; }
    else          { off = base + (TT - 1) * CC;  dt = -CC; o = wb; }
    for (int t = 0; t < TT; ++t, off += dt) {
        float kk = k[off], vv = v[off];
        float uk = uu + kk;
        float q  = fmaxf(pp, uk);
        float e1 = __expf(pp - q), e2 = __expf(uk - q);
        o[off] = (e1 * aa + e2 * vv) / (e1 * bbv + e2);
        float pw = pp + w;
        float q2 = fmaxf(pw, kk);
        float f1 = __expf(pw - q2), f2 = __expf(kk - q2);
        aa  = f1 * aa  + f2 * vv;
        bbv = f1 * bbv + f2;
        pp  = q2;
    }
}

// mix: rh <- fp16(r * 0.5 * (wf + wb))
__global__ void mix_kernel(const float* __restrict__ r,
                           const float* __restrict__ wf,
                           const float* __restrict__ wb,
                           __half* __restrict__ rh) {
    int i = (blockIdx.x * blockDim.x + threadIdx.x) * 2;
    float2 rv = *(const float2*)(r + i);
    float2 fv = *(const float2*)(wf + i);
    float2 bv = *(const float2*)(wb + i);
    *(__half2*)(rh + i) = __floats2half2_rn(rv.x * 0.5f * (fv.x + bv.x),
                                            rv.y * 0.5f * (fv.y + bv.y));
}

// ---------------------------------------------------------------------------
// Launch
// ---------------------------------------------------------------------------
extern "C" void kernel_launch(void* const* d_in, const int* in_sizes, int n_in,
                              void* d_out, int out_size) {
    const float* x     = (const float*)d_in[0];
    const float* ln1w  = (const float*)d_in[1];
    const float* ln1b  = (const float*)d_in[2];
    const float* ln2w  = (const float*)d_in[3];
    const float* ln2b  = (const float*)d_in[4];
    const float* Wr    = (const float*)d_in[5];
    const float* Wk    = (const float*)d_in[6];
    const float* Wv    = (const float*)d_in[7];
    const float* Wo    = (const float*)d_in[8];
    const float* decay = (const float*)d_in[9];
    const float* u     = (const float*)d_in[10];
    const float* Wfk   = (const float*)d_in[11];
    const float* Wfv   = (const float*)d_in[12];
    const float* Wfr   = (const float*)d_in[13];
    float* out = (float*)d_out;

    float *r, *k, *v, *wf, *wb;
    __half *xnh, *rh, *kkh, *hWr, *hWk, *hWv, *hWo, *hWfk, *hWfv, *hWfr;
    cudaGetSymbolAddress((void**)&r,   g_r);
    cudaGetSymbolAddress((void**)&k,   g_k);
    cudaGetSymbolAddress((void**)&v,   g_v);
    cudaGetSymbolAddress((void**)&wf,  g_wf);
    cudaGetSymbolAddress((void**)&wb,  g_wb);
    cudaGetSymbolAddress((void**)&xnh, g_xnh);
    cudaGetSymbolAddress((void**)&rh,  g_rh);
    cudaGetSymbolAddress((void**)&kkh, g_kkh);
    cudaGetSymbolAddress((void**)&hWr,  g_w1);
    cudaGetSymbolAddress((void**)&hWk,  g_w2);
    cudaGetSymbolAddress((void**)&hWv,  g_w3);
    cudaGetSymbolAddress((void**)&hWo,  g_w4);
    cudaGetSymbolAddress((void**)&hWfk, g_w5);
    cudaGetSymbolAddress((void**)&hWfv, g_w6);
    cudaGetSymbolAddress((void**)&hWfr, g_w7);

    const int smem = 2 * STG_BYTES + 256;  // 64KB + align pad
    cudaFuncSetAttribute(gemm_h<EPI_NONE>,    cudaFuncAttributeMaxDynamicSharedMemorySize, smem);
    cudaFuncSetAttribute(gemm_h<EPI_SIGMOID>, cudaFuncAttributeMaxDynamicSharedMemorySize, smem);
    cudaFuncSetAttribute(gemm_h<EPI_RELU2>,   cudaFuncAttributeMaxDynamicSharedMemorySize, smem);
    cudaFuncSetAttribute(gemm_h<EPI_ADD>,     cudaFuncAttributeMaxDynamicSharedMemorySize, smem);
    cudaFuncSetAttribute(gemm_h<EPI_MADD>,    cudaFuncAttributeMaxDynamicSharedMemorySize, smem);

    // 0) convert weights to fp16 once
    cvt_h_kernel<<<CC*CC/1024, 256>>>(Wr,  hWr);
    cvt_h_kernel<<<CC*CC/1024, 256>>>(Wk,  hWk);
    cvt_h_kernel<<<CC*CC/1024, 256>>>(Wv,  hWv);
    cvt_h_kernel<<<CC*CC/1024, 256>>>(Wo,  hWo);
    cvt_h_kernel<<<C4*CC/1024, 256>>>(Wfk, hWfk);
    cvt_h_kernel<<<C4*CC/1024, 256>>>(Wfv, hWfv);
    cvt_h_kernel<<<CC*CC/1024, 256>>>(Wfr, hWfr);

    dim3 gC (CC / 128, MM / 128);    // (8, 64)
    dim3 g4C(C4 / 128, MM / 128);    // (32, 64)

    // 1) ln1 -> fp16
    ln_kernel<<<MM, 256>>>(x, ln1w, ln1b, xnh);
    // 2) r, k, v projections
    gemm_h<EPI_SIGMOID><<<gC, 256, smem>>>(xnh, hWr, r, nullptr, nullptr, nullptr, MM, CC, CC);
    gemm_h<EPI_NONE>   <<<gC, 256, smem>>>(xnh, hWk, k, nullptr, nullptr, nullptr, MM, CC, CC);
    gemm_h<EPI_NONE>   <<<gC, 256, smem>>>(xnh, hWv, v, nullptr, nullptr, nullptr, MM, CC, CC);
    // 3) bidirectional wkv scan
    scan_kernel<<<dim3(BBATCH * CC / 256, 2), 256>>>(decay, u, k, v, wf, wb);
    // 4) rh = fp16(r * 0.5*(wf+wb))
    mix_kernel<<<(MM * CC) / 512, 256>>>(r, wf, wb, rh);
    // 5) out = x + (r*wkv) @ Wo^T
    gemm_h<EPI_ADD>    <<<gC, 256, smem>>>(rh, hWo, out, nullptr, x, nullptr, MM, CC, CC);
    // 6) ln2 -> fp16
    ln_kernel<<<MM, 256>>>(out, ln2w, ln2b, xnh);
    // 7) kk = fp16(relu(xn2 @ Wfk^T)^2)
    gemm_h<EPI_RELU2>  <<<g4C, 256, smem>>>(xnh, hWfk, nullptr, kkh, nullptr, nullptr, MM, C4, CC);
    // 8) s = sigmoid(xn2 @ Wfr^T)  (stored in v)
    gemm_h<EPI_SIGMOID><<<gC, 256, smem>>>(xnh, hWfr, v, nullptr, nullptr, nullptr, MM, CC, CC);
    // 9) out += s * (kk @ Wfv^T)
    gemm_h<EPI_MADD>   <<<gC, 256, smem>>>(kkh, hWfv, out, nullptr, out, v, MM, CC, C4);
}